// round 3
// baseline (speedup 1.0000x reference)
#include <cuda_runtime.h>

#define KDIM 64
#define SDIM 512
#define TILE_I 64
#define TILE_S 128
#define PITCH 68          // floats per smem row; float4 lane-stride 17 (mod 8) -> conflict-free
#define NT 128
#define NTILES (SDIM / TILE_S)
#define MAXBLOCKS 2048

typedef unsigned long long ull;

__device__ float g_partial[MAXBLOCKS];

__device__ __forceinline__ void ffma2(ull& d, ull a, ull b) {
    asm volatile("fma.rn.f32x2 %0, %1, %2, %0;" : "+l"(d) : "l"(a), "l"(b));
}
__device__ __forceinline__ void cp16(float* dst, const float* src) {
    unsigned d = (unsigned)__cvta_generic_to_shared(dst);
    asm volatile("cp.async.cg.shared.global [%0], [%1], 16;" :: "r"(d), "l"(src));
}
__device__ __forceinline__ void cp_commit() { asm volatile("cp.async.commit_group;"); }

// ---------------------------------------------------------------------------
// Main: tiled fp32x2 GEMM + fused argmin (reference rounding) + gather + loss
// CTA: 64 vectors x 512 codewords (4 s-tiles of 128, double buffered)
// Thread tile: 8 vectors x 8 codewords (tx: 16 threads s-dir, ty: 8 threads i-dir)
// All smem operand loads are LDS.128, conflict-free.
// Score d = fl(fl(vn - 2*dot) + cn), argmin tie-break = lowest s (u64 key)
// ---------------------------------------------------------------------------
__global__ void __launch_bounds__(NT, 2)
vq_main(const float* __restrict__ vecs, const float* __restrict__ cb,
        float* __restrict__ out, int N)
{
    extern __shared__ float sm[];
    float* vt     = sm;                                  // TILE_I * PITCH
    float* ct     = vt + TILE_I * PITCH;                 // 2 * TILE_S * PITCH
    float* cnorm  = ct + 2 * TILE_S * PITCH;             // SDIM
    ull*   kbuf   = (ull*)(cnorm + SDIM);                // 64*17 (8B aligned)
    float* sv     = (float*)(kbuf + 64 * 17);            // 64
    int*   bidx   = (int*)(sv + 64);                     // 64
    float* redsum = (float*)(bidx + 64);                 // 64

    const int tid = threadIdx.x;
    const int tx = tid & 15;      // codeword direction (16 threads)
    const int ty = tid >> 4;      // vector direction   (8 threads)
    const long i0 = (long)blockIdx.x * TILE_I;

    // Prologue: async-load vector tile + first codebook tile (group 0)
    {
        const float* vsrc = vecs + i0 * KDIM;
        for (int n = tid; n < TILE_I * (KDIM / 4); n += NT) {
            int row = n >> 4, c4 = n & 15;
            cp16(vt + row * PITCH + c4 * 4, vsrc + row * KDIM + c4 * 4);
        }
        for (int n = tid; n < TILE_S * (KDIM / 4); n += NT) {
            int row = n >> 4, c4 = n & 15;
            cp16(ct + row * PITCH + c4 * 4, cb + row * KDIM + c4 * 4);
        }
        cp_commit();
    }

    // Codebook norms (redundant per CTA; codebook is L2-resident). Sequential
    // fmaf in x,y,z,w order — same rounding as before.
    #pragma unroll
    for (int r = 0; r < SDIM / NT; r++) {
        int s = r * NT + tid;
        const float4* row = (const float4*)(cb + (long)s * KDIM);
        float acc = 0.f;
        #pragma unroll
        for (int q = 0; q < KDIM / 4; q++) {
            float4 v = __ldg(row + q);
            acc = fmaf(v.x, v.x, acc);
            acc = fmaf(v.y, v.y, acc);
            acc = fmaf(v.z, v.z, acc);
            acc = fmaf(v.w, v.w, acc);
        }
        cnorm[s] = acc;
    }

    // Per-vector squared norms from gmem (L2-hit: cp.async touched same lines)
    if (tid < TILE_I) {
        const float4* r = (const float4*)(vecs + (i0 + tid) * KDIM);
        float acc = 0.f;
        #pragma unroll
        for (int q = 0; q < KDIM / 4; q++) {
            float4 v = __ldg(r + q);
            acc = fmaf(v.x, v.x, acc);
            acc = fmaf(v.y, v.y, acc);
            acc = fmaf(v.z, v.z, acc);
            acc = fmaf(v.w, v.w, acc);
        }
        sv[tid] = acc;
    }

    ull bestkey = ~0ull;   // running (score|index) min for vector `tid` (tid<64)

    for (int t = 0; t < NTILES; ++t) {
        // Prefetch next codebook tile, then wait for current one
        if (t + 1 < NTILES) {
            const float* csrc = cb + (long)(t + 1) * TILE_S * KDIM;
            float* cdst = ct + ((t + 1) & 1) * TILE_S * PITCH;
            for (int n = tid; n < TILE_S * (KDIM / 4); n += NT) {
                int row = n >> 4, c4 = n & 15;
                cp16(cdst + row * PITCH + c4 * 4, csrc + row * KDIM + c4 * 4);
            }
            cp_commit();
            asm volatile("cp.async.wait_group 1;");
        } else {
            asm volatile("cp.async.wait_group 0;");
        }
        __syncthreads();   // publishes tile, cnorm, sv; closes previous merge

        const float* cbt  = ct + (t & 1) * TILE_S * PITCH;
        const float* vrow = vt + (ty * 8) * PITCH;
        const float* crow = cbt + tx * PITCH;

        ull acc[8][8];
        #pragma unroll
        for (int a = 0; a < 8; a++)
            #pragma unroll
            for (int b = 0; b < 8; b++) acc[a][b] = 0ull;

        #pragma unroll 4
        for (int kc = 0; kc < KDIM / 4; ++kc) {
            ulonglong2 av[8], bv[8];
            #pragma unroll
            for (int ii = 0; ii < 8; ii++)
                av[ii] = *(const ulonglong2*)(vrow + ii * PITCH + kc * 4);
            #pragma unroll
            for (int jj = 0; jj < 8; jj++)
                bv[jj] = *(const ulonglong2*)(crow + jj * 16 * PITCH + kc * 4);
            #pragma unroll
            for (int ii = 0; ii < 8; ii++)
                #pragma unroll
                for (int jj = 0; jj < 8; jj++) {
                    ffma2(acc[ii][jj], av[ii].x, bv[jj].x);
                    ffma2(acc[ii][jj], av[ii].y, bv[jj].y);
                }
        }

        // Per-thread min over its 8 codewords with reference rounding:
        //   d = fl( fl(vn - 2*dot) + cn ),  key = (bits(d)<<32) | s
        #pragma unroll
        for (int ii = 0; ii < 8; ii++) {
            float vn = sv[ty * 8 + ii];
            ull bk = ~0ull;
            #pragma unroll
            for (int jj = 0; jj < 8; jj++) {
                float lo = __uint_as_float((unsigned)(acc[ii][jj] & 0xffffffffull));
                float hi = __uint_as_float((unsigned)(acc[ii][jj] >> 32));
                float dot = lo + hi;
                int s = t * TILE_S + jj * 16 + tx;
                float t1 = __fmaf_rn(-2.0f, dot, vn);          // fl(vn - 2*dot)
                float d  = __fadd_rn(t1, cnorm[s]);
                ull key = ((ull)__float_as_uint(d) << 32) | (unsigned)s;
                bk = key < bk ? key : bk;
            }
            kbuf[(ty * 8 + ii) * 17 + tx] = bk;
        }
        __syncthreads();
        // Cross-thread merge (one thread per vector keeps running best)
        if (tid < TILE_I) {
            #pragma unroll
            for (int x = 0; x < 16; x++) {
                ull k = kbuf[tid * 17 + x];
                bestkey = k < bestkey ? k : bestkey;
            }
        }
        __syncthreads();
    }

    // Final epilogue: err, z, loss partial
    float* out_z = out + (long)N * KDIM;
    if (tid < TILE_I) {
        float d = __uint_as_float((unsigned)(bestkey >> 32));
        int   z = (int)(bestkey & 0xffffffffull);
        float err = fmaxf(d, 0.0f);
        out_z[i0 + tid] = (float)z;
        bidx[tid] = z;
        redsum[tid] = err;
    }
    __syncthreads();

    // Gather codewords: vecs_hat = codebook[z]
    for (int n = tid; n < TILE_I * KDIM; n += NT) {
        int row = n >> 6, col = n & 63;
        out[(i0 + row) * KDIM + col] = __ldg(&cb[(long)bidx[row] * KDIM + col]);
    }

    if (tid == 0) {
        float s = 0.f;
        #pragma unroll 8
        for (int x = 0; x < TILE_I; x++) s += redsum[x];
        g_partial[blockIdx.x] = s;
    }
}

// ---------------------------------------------------------------------------
// Final: deterministic reduction of per-CTA partials -> both loss scalars
// ---------------------------------------------------------------------------
__global__ void vq_final(float* __restrict__ out, int N, int nblocks) {
    __shared__ float smr[256];
    float s = 0.f;
    for (int i = threadIdx.x; i < nblocks; i += 256) s += g_partial[i];
    smr[threadIdx.x] = s;
    __syncthreads();
    if (threadIdx.x == 0) {
        double tot = 0.0;
        for (int i = 0; i < 256; i++) tot += (double)smr[i];
        float mean = (float)(tot / (double)N);
        long base = (long)N * KDIM + N;
        out[base]     = mean;   // l_commit
        out[base + 1] = mean;   // l_codebook (identical forward value)
    }
}

extern "C" void kernel_launch(void* const* d_in, const int* in_sizes, int n_in,
                              void* d_out, int out_size) {
    const float* vecs = (const float*)d_in[0];
    const float* cb   = (const float*)d_in[1];
    float* out = (float*)d_out;

    int N = in_sizes[0] / KDIM;          // 65536
    int nblocks = N / TILE_I;            // 1024

    size_t smem_bytes =
        (size_t)(TILE_I * PITCH + 2 * TILE_S * PITCH + SDIM) * sizeof(float)
        + (size_t)(64 * 17) * sizeof(ull)
        + (size_t)64 * sizeof(float)     // sv
        + (size_t)64 * sizeof(int)       // bidx
        + (size_t)64 * sizeof(float);    // redsum

    cudaFuncSetAttribute(vq_main, cudaFuncAttributeMaxDynamicSharedMemorySize,
                         (int)smem_bytes);

    vq_main<<<nblocks, NT, smem_bytes>>>(vecs, cb, out, N);
    vq_final<<<1, 256>>>(out, N, nblocks);
}

// round 4
// speedup vs baseline: 1.3145x; 1.3145x over previous
#include <cuda_runtime.h>

#define KDIM 64
#define SDIM 512
#define TILE_I 64
#define NT 512
#define PITCH 68            // floats/row: 272B; float4 lane-stride 17 (mod 8) -> conflict-free
#define NWARP 16
#define CW_PER_WARP 32      // SDIM / NWARP
#define CHUNK 16            // codewords per register chunk
#define NCHUNK (CW_PER_WARP / CHUNK)
#define GRID 148

typedef unsigned long long ull;

__device__ float    g_partial[GRID];
__device__ unsigned g_ticket;   // zero-init; reset to 0 by last CTA each launch

__device__ __forceinline__ void ffma2(ull& d, ull a, ull b) {
    asm volatile("fma.rn.f32x2 %0, %1, %2, %0;" : "+l"(d) : "l"(a), "l"(b));
}
__device__ __forceinline__ void cp16(float* dst, const float* src) {
    unsigned d = (unsigned)__cvta_generic_to_shared(dst);
    asm volatile("cp.async.cg.shared.global [%0], [%1], 16;" :: "r"(d), "l"(src));
}
__device__ __forceinline__ void cp_commit() { asm volatile("cp.async.commit_group;"); }

// ---------------------------------------------------------------------------
// Persistent fused kernel.
//  - whole codebook (512 x 64 f32) resident in smem, loaded once per CTA
//  - vector tiles of 64 streamed with cp.async double buffering
//  - warp w owns codewords [32w, 32w+32); lane L owns vectors L and L+32
//    -> codeword smem loads are warp-broadcast (1 crossbar cycle each)
//  - score d = fl(fl(vn - 2*dot) + cn); argmin tie-break lowest s via u64 key
//  - losses reduced in-kernel (ticket; last CTA writes scalars)
// ---------------------------------------------------------------------------
__global__ void __launch_bounds__(NT, 1)
vq_fused(const float* __restrict__ vecs, const float* __restrict__ cb,
         float* __restrict__ out, int N, int ntiles, int nctas)
{
    extern __shared__ float sm[];
    float* ct     = sm;                           // SDIM * PITCH
    float* vt     = ct + SDIM * PITCH;            // 2 * TILE_I * PITCH
    float* cnorm  = vt + 2 * TILE_I * PITCH;      // SDIM
    float* sv     = cnorm + SDIM;                 // TILE_I
    ull*   kbuf   = (ull*)(sv + TILE_I);          // TILE_I * 17  (8B aligned)
    float* redsum = (float*)(kbuf + TILE_I * 17); // TILE_I
    int*   bidx   = (int*)(redsum + TILE_I);      // TILE_I

    const int tid  = threadIdx.x;
    const int lane = tid & 31;
    const int wid  = tid >> 5;

    // ---- prologue: codebook -> smem (once), first vector tile, cnorm ----
    for (int n = tid; n < SDIM * (KDIM / 4); n += NT) {
        int row = n >> 4, c4 = n & 15;
        cp16(ct + row * PITCH + c4 * 4, cb + row * KDIM + c4 * 4);
    }
    {
        const float* vsrc = vecs + (long)blockIdx.x * TILE_I * KDIM;
        for (int n = tid; n < TILE_I * (KDIM / 4); n += NT) {
            int row = n >> 4, c4 = n & 15;
            cp16(vt + row * PITCH + c4 * 4, vsrc + row * KDIM + c4 * 4);
        }
    }
    cp_commit();

    // codebook norms: one row per thread, sequential fmaf in x,y,z,w order
    {
        const float4* row = (const float4*)(cb + (long)tid * KDIM);
        float acc = 0.f;
        #pragma unroll
        for (int q = 0; q < KDIM / 4; q++) {
            float4 v = __ldg(row + q);
            acc = fmaf(v.x, v.x, acc);
            acc = fmaf(v.y, v.y, acc);
            acc = fmaf(v.z, v.z, acc);
            acc = fmaf(v.w, v.w, acc);
        }
        cnorm[tid] = acc;
    }

    float csum = 0.f;   // thread 0: running loss sum across this CTA's tiles
    int buf = 0;
    float* out_z = out + (long)N * KDIM;

    for (long tile = blockIdx.x; tile < ntiles; tile += nctas) {
        asm volatile("cp.async.wait_group 0;");
        __syncthreads();

        // prefetch next vector tile into the other buffer
        long tnext = tile + nctas;
        if (tnext < ntiles) {
            const float* vsrc = vecs + tnext * TILE_I * KDIM;
            float* dst = vt + (buf ^ 1) * TILE_I * PITCH;
            for (int n = tid; n < TILE_I * (KDIM / 4); n += NT) {
                int row = n >> 4, c4 = n & 15;
                cp16(dst + row * PITCH + c4 * 4, vsrc + row * KDIM + c4 * 4);
            }
        }
        cp_commit();

        const float* vtb = vt + buf * TILE_I * PITCH;

        // per-vector norms from smem (same fmaf order as before)
        if (tid < TILE_I) {
            const float* vr = vtb + tid * PITCH;
            float acc = 0.f;
            #pragma unroll
            for (int q = 0; q < KDIM / 4; q++) {
                float4 v = *(const float4*)(vr + q * 4);
                acc = fmaf(v.x, v.x, acc);
                acc = fmaf(v.y, v.y, acc);
                acc = fmaf(v.z, v.z, acc);
                acc = fmaf(v.w, v.w, acc);
            }
            sv[tid] = acc;
        }
        __syncthreads();

        ull best0 = ~0ull, best1 = ~0ull;
        const float* arow0 = vtb + lane * PITCH;
        const float* arow1 = vtb + (lane + 32) * PITCH;

        #pragma unroll 1
        for (int ch = 0; ch < NCHUNK; ch++) {
            const int cw0 = wid * CW_PER_WARP + ch * CHUNK;
            const float* brow = ct + cw0 * PITCH;

            ull acc[2][CHUNK];
            #pragma unroll
            for (int j = 0; j < CHUNK; j++) { acc[0][j] = 0ull; acc[1][j] = 0ull; }

            #pragma unroll
            for (int kc = 0; kc < KDIM / 4; kc++) {
                ulonglong2 a0 = *(const ulonglong2*)(arow0 + kc * 4);
                ulonglong2 a1 = *(const ulonglong2*)(arow1 + kc * 4);
                #pragma unroll
                for (int j = 0; j < CHUNK; j++) {
                    ulonglong2 b = *(const ulonglong2*)(brow + j * PITCH + kc * 4);
                    ffma2(acc[0][j], a0.x, b.x);
                    ffma2(acc[0][j], a0.y, b.y);
                    ffma2(acc[1][j], a1.x, b.x);
                    ffma2(acc[1][j], a1.y, b.y);
                }
            }

            // score with reference rounding; tie-break lowest s
            float vn0 = sv[lane], vn1 = sv[lane + 32];
            #pragma unroll
            for (int j = 0; j < CHUNK; j++) {
                int s = cw0 + j;
                float cn = cnorm[s];
                {
                    float lo = __uint_as_float((unsigned)(acc[0][j] & 0xffffffffull));
                    float hi = __uint_as_float((unsigned)(acc[0][j] >> 32));
                    float dot = lo + hi;
                    float d = __fadd_rn(__fmaf_rn(-2.0f, dot, vn0), cn);
                    ull key = ((ull)__float_as_uint(d) << 32) | (unsigned)s;
                    best0 = key < best0 ? key : best0;
                }
                {
                    float lo = __uint_as_float((unsigned)(acc[1][j] & 0xffffffffull));
                    float hi = __uint_as_float((unsigned)(acc[1][j] >> 32));
                    float dot = lo + hi;
                    float d = __fadd_rn(__fmaf_rn(-2.0f, dot, vn1), cn);
                    ull key = ((ull)__float_as_uint(d) << 32) | (unsigned)s;
                    best1 = key < best1 ? key : best1;
                }
            }
        }

        kbuf[lane * 17 + wid]        = best0;
        kbuf[(lane + 32) * 17 + wid] = best1;
        __syncthreads();

        const long i0 = tile * TILE_I;
        if (tid < TILE_I) {
            ull bk = kbuf[tid * 17];
            #pragma unroll
            for (int w = 1; w < NWARP; w++) {
                ull k = kbuf[tid * 17 + w];
                bk = k < bk ? k : bk;
            }
            float d = __uint_as_float((unsigned)(bk >> 32));
            int   z = (int)(bk & 0xffffffffull);
            out_z[i0 + tid] = (float)z;
            bidx[tid] = z;
            redsum[tid] = fmaxf(d, 0.0f);
        }
        __syncthreads();

        // gather vecs_hat = codebook[z] straight from smem ct
        for (int n = tid; n < TILE_I * KDIM; n += NT) {
            int row = n >> 6, col = n & 63;
            out[(i0 + row) * KDIM + col] = ct[bidx[row] * PITCH + col];
        }
        if (tid == 0) {
            float s = 0.f;
            #pragma unroll 8
            for (int x = 0; x < TILE_I; x++) s += redsum[x];
            csum += s;
        }
        buf ^= 1;
        __syncthreads();
    }

    // ---- in-kernel deterministic loss reduction ----
    if (tid == 0) {
        g_partial[blockIdx.x] = csum;
        __threadfence();
        unsigned t = atomicAdd(&g_ticket, 1u);
        if (t == (unsigned)(nctas - 1)) {
            double tot = 0.0;
            for (int i = 0; i < nctas; i++)
                tot += (double)(*(volatile float*)&g_partial[i]);
            float mean = (float)(tot / (double)N);
            long base = (long)N * KDIM + N;
            out[base]     = mean;   // l_commit
            out[base + 1] = mean;   // l_codebook (identical forward value)
            g_ticket = 0;           // reset for next graph replay
        }
    }
}

extern "C" void kernel_launch(void* const* d_in, const int* in_sizes, int n_in,
                              void* d_out, int out_size) {
    const float* vecs = (const float*)d_in[0];
    const float* cb   = (const float*)d_in[1];
    float* out = (float*)d_out;

    int N = in_sizes[0] / KDIM;          // 65536
    int ntiles = N / TILE_I;             // 1024
    int nctas = ntiles < GRID ? ntiles : GRID;

    size_t smem_bytes =
        (size_t)(SDIM * PITCH + 2 * TILE_I * PITCH + SDIM + TILE_I) * sizeof(float)
        + (size_t)(TILE_I * 17) * sizeof(ull)
        + (size_t)TILE_I * sizeof(float)      // redsum
        + (size_t)TILE_I * sizeof(int);       // bidx

    cudaFuncSetAttribute(vq_fused, cudaFuncAttributeMaxDynamicSharedMemorySize,
                         (int)smem_bytes);

    vq_fused<<<nctas, NT, smem_bytes>>>(vecs, cb, out, N, ntiles, nctas);
}